// round 1
// baseline (speedup 1.0000x reference)
#include <cuda_runtime.h>
#include <math.h>

#define BB 256
#define TT 256
#define CC 1024
#define DD 64
#define BT (BB*TT)

// Scratch for Q, K, V (16 MB each)
__device__ float g_q[BT*DD];
__device__ float g_k[BT*DD];
__device__ float g_v[BT*DD];

// ---------------------------------------------------------------------------
// Kernel A: fused QKV projection.
// Grid: BT/64 = 1024 blocks, 256 threads (16x16 logical).
// Each block: 64 rows of x  x  192 output cols (Q|K|V, 64 each).
// K-chunks of 32 staged in shared. Register tile 4x12 per thread.
// ---------------------------------------------------------------------------
#define TM 64
#define KC 32

__global__ __launch_bounds__(256) void qkv_kernel(
    const float* __restrict__ x,
    const float* __restrict__ Wq,
    const float* __restrict__ Wk,
    const float* __restrict__ Wv)
{
    __shared__ float sx[KC][TM];    // [k][m]
    __shared__ float sw[KC][192];   // [k][n]  n: 0..63 Q, 64..127 K, 128..191 V

    const int tid = threadIdx.x;
    const int tx  = tid & 15;       // col group
    const int ty  = tid >> 4;       // row group
    const int row0 = blockIdx.x * TM;

    float acc[4][12];
    #pragma unroll
    for (int i = 0; i < 4; i++)
        #pragma unroll
        for (int j = 0; j < 12; j++) acc[i][j] = 0.f;

    for (int kc = 0; kc < CC; kc += KC) {
        // --- load x tile: 64 rows x 32 cols = 512 float4, 2 per thread ---
        #pragma unroll
        for (int l = 0; l < 2; l++) {
            int idx = tid + l * 256;          // 0..511
            int r   = idx >> 3;               // 0..63
            int c4  = idx & 7;                // 0..7
            float4 v = *(const float4*)&x[(size_t)(row0 + r) * CC + kc + c4 * 4];
            sx[c4*4+0][r] = v.x;
            sx[c4*4+1][r] = v.y;
            sx[c4*4+2][r] = v.z;
            sx[c4*4+3][r] = v.w;
        }
        // --- load W tiles: 3 x (32 rows x 64 cols) = 1536 float4, 6 per thread ---
        #pragma unroll
        for (int l = 0; l < 6; l++) {
            int idx = tid + l * 256;          // 0..1535
            const float* W = (l < 2) ? Wq : ((l < 4) ? Wk : Wv);
            int m   = (l < 2) ? 0 : ((l < 4) ? 1 : 2);
            int rem = idx & 511;              // 0..511 within matrix
            int r   = rem >> 4;               // 0..31
            int c4  = rem & 15;               // 0..15
            float4 v = *(const float4*)&W[(size_t)(kc + r) * DD + c4 * 4];
            sw[r][m*64 + c4*4+0] = v.x;
            sw[r][m*64 + c4*4+1] = v.y;
            sw[r][m*64 + c4*4+2] = v.z;
            sw[r][m*64 + c4*4+3] = v.w;
        }
        __syncthreads();

        #pragma unroll 4
        for (int kk = 0; kk < KC; kk++) {
            float a[4];
            #pragma unroll
            for (int i = 0; i < 4; i++) a[i] = sx[kk][ty*4 + i];
            float b[12];
            #pragma unroll
            for (int j = 0; j < 12; j++)
                b[j] = sw[kk][(j >> 2)*64 + tx + (j & 3)*16];
            #pragma unroll
            for (int i = 0; i < 4; i++)
                #pragma unroll
                for (int j = 0; j < 12; j++)
                    acc[i][j] = fmaf(a[i], b[j], acc[i][j]);
        }
        __syncthreads();
    }

    // --- write out Q, K, V ---
    #pragma unroll
    for (int i = 0; i < 4; i++) {
        size_t r = (size_t)(row0 + ty*4 + i) * DD;
        #pragma unroll
        for (int j = 0; j < 4; j++) {
            g_q[r + tx + j*16] = acc[i][j];
            g_k[r + tx + j*16] = acc[i][4 + j];
            g_v[r + tx + j*16] = acc[i][8 + j];
        }
    }
}

// ---------------------------------------------------------------------------
// Kernel B: causal attention, one block per (batch, 64-query tile).
// Full K/V/Q^T/scores in dynamic shared (~208.5 KB).
// ---------------------------------------------------------------------------
#define SQT_STRIDE 65
#define SP_STRIDE  257
#define SMEM_FLOATS (64*SQT_STRIDE + 256*64 + 256*64 + 64*SP_STRIDE)
#define SMEM_BYTES  (SMEM_FLOATS * 4)

__global__ __launch_bounds__(256) void attn_kernel(float* __restrict__ out)
{
    extern __shared__ float sm[];
    float* sQt = sm;                        // [d][r], stride 65 (Q transposed)
    float* sK  = sQt + 64 * SQT_STRIDE;     // [s][d]
    float* sV  = sK  + 256 * 64;            // [s][d]
    float* sP  = sV  + 256 * 64;            // [r][s], stride 257

    const int tid = threadIdx.x;
    const int bb  = blockIdx.y;             // batch
    const int q0  = blockIdx.x * 64;        // query tile offset

    // --- load K, V: 256x64 each = 4096 float4 each, 16 per thread ---
    const float* kbase = g_k + (size_t)bb * TT * DD;
    const float* vbase = g_v + (size_t)bb * TT * DD;
    #pragma unroll
    for (int l = 0; l < 16; l++) {
        int idx = tid + l * 256;            // 0..4095
        int s   = idx >> 4;
        int d4  = idx & 15;
        *(float4*)&sK[s*64 + d4*4] = *(const float4*)&kbase[s*DD + d4*4];
        *(float4*)&sV[s*64 + d4*4] = *(const float4*)&vbase[s*DD + d4*4];
    }
    // --- load Q transposed: 64x64 = 1024 float4, 4 per thread ---
    const float* qbase = g_q + (size_t)(bb * TT + q0) * DD;
    #pragma unroll
    for (int l = 0; l < 4; l++) {
        int idx = tid + l * 256;            // 0..1023
        int r   = idx >> 4;
        int d4  = idx & 15;
        float4 qv = *(const float4*)&qbase[r*DD + d4*4];
        sQt[(d4*4+0)*SQT_STRIDE + r] = qv.x;
        sQt[(d4*4+1)*SQT_STRIDE + r] = qv.y;
        sQt[(d4*4+2)*SQT_STRIDE + r] = qv.z;
        sQt[(d4*4+3)*SQT_STRIDE + r] = qv.w;
    }
    __syncthreads();

    // --- scores: rows r = tx + 16*i (i<4), cols s = ty*16 + j (j<16) ---
    const int tx = tid & 15;
    const int ty = tid >> 4;
    {
        float acc[4][16];
        #pragma unroll
        for (int i = 0; i < 4; i++)
            #pragma unroll
            for (int j = 0; j < 16; j++) acc[i][j] = 0.f;

        #pragma unroll 4
        for (int d = 0; d < 64; d++) {
            float a[4];
            #pragma unroll
            for (int i = 0; i < 4; i++) a[i] = sQt[d*SQT_STRIDE + tx + 16*i];
            float b[16];
            #pragma unroll
            for (int j = 0; j < 16; j++) b[j] = sK[(ty*16 + j)*64 + d];
            #pragma unroll
            for (int i = 0; i < 4; i++)
                #pragma unroll
                for (int j = 0; j < 16; j++)
                    acc[i][j] = fmaf(a[i], b[j], acc[i][j]);
        }

        const float scale = 0.03125f;   // C^-0.5 = 1/32
        #pragma unroll
        for (int i = 0; i < 4; i++) {
            int r = tx + 16*i;
            #pragma unroll
            for (int j = 0; j < 16; j++) {
                int s = ty*16 + j;
                float sc = acc[i][j] * scale;
                if (s > q0 + r) sc = -INFINITY;   // causal mask (global query idx)
                sP[r*SP_STRIDE + s] = sc;
            }
        }
    }
    __syncthreads();

    // --- softmax: one thread per row (64 rows), stride-257 rows are conflict-free ---
    if (tid < 64) {
        float m = -INFINITY;
        for (int s = 0; s < 256; s++) m = fmaxf(m, sP[tid*SP_STRIDE + s]);
        float sum = 0.f;
        for (int s = 0; s < 256; s++) {
            float e = expf(sP[tid*SP_STRIDE + s] - m);
            sP[tid*SP_STRIDE + s] = e;
            sum += e;
        }
        float inv = 1.f / sum;
        for (int s = 0; s < 256; s++) sP[tid*SP_STRIDE + s] *= inv;
    }
    __syncthreads();

    // --- AV: rows r = ty*4+i, cols d = tx*4+j ---
    {
        float oacc[4][4];
        #pragma unroll
        for (int i = 0; i < 4; i++)
            #pragma unroll
            for (int j = 0; j < 4; j++) oacc[i][j] = 0.f;

        #pragma unroll 4
        for (int s = 0; s < 256; s++) {
            float4 bv = *(const float4*)&sV[s*64 + tx*4];
            float a[4];
            #pragma unroll
            for (int i = 0; i < 4; i++) a[i] = sP[(ty*4 + i)*SP_STRIDE + s];
            #pragma unroll
            for (int i = 0; i < 4; i++) {
                oacc[i][0] = fmaf(a[i], bv.x, oacc[i][0]);
                oacc[i][1] = fmaf(a[i], bv.y, oacc[i][1]);
                oacc[i][2] = fmaf(a[i], bv.z, oacc[i][2]);
                oacc[i][3] = fmaf(a[i], bv.w, oacc[i][3]);
            }
        }

        #pragma unroll
        for (int i = 0; i < 4; i++) {
            size_t o = (size_t)(bb * TT + q0 + ty*4 + i) * DD + tx*4;
            float4 v = make_float4(oacc[i][0], oacc[i][1], oacc[i][2], oacc[i][3]);
            *(float4*)&out[o] = v;
        }
    }
}

// ---------------------------------------------------------------------------
extern "C" void kernel_launch(void* const* d_in, const int* in_sizes, int n_in,
                              void* d_out, int out_size)
{
    (void)in_sizes; (void)n_in; (void)out_size;
    const float* x  = (const float*)d_in[0];
    const float* Wq = (const float*)d_in[1];
    const float* Wk = (const float*)d_in[2];
    const float* Wv = (const float*)d_in[3];
    float* out = (float*)d_out;

    cudaFuncSetAttribute(attn_kernel,
                         cudaFuncAttributeMaxDynamicSharedMemorySize, SMEM_BYTES);

    qkv_kernel<<<BT / TM, 256>>>(x, Wq, Wk, Wv);
    attn_kernel<<<dim3(4, BB), 256, SMEM_BYTES>>>(out);
}

// round 3
// speedup vs baseline: 2.3503x; 2.3503x over previous
#include <cuda_runtime.h>
#include <math.h>
#include <cstdint>

#define BB 256
#define TT 256
#define CC 1024
#define DD 64
#define BT (BB*TT)

// Scratch for Q, K, V (16 MB each)
__device__ float g_q[BT*DD];
__device__ float g_k[BT*DD];
__device__ float g_v[BT*DD];

// ===================== mma.sync helpers (sm_80+ PTX, ok on compute_103) ====
__device__ __forceinline__ uint32_t f32_to_tf32(float f) {
    uint32_t u;
    asm("cvt.rna.tf32.f32 %0, %1;" : "=r"(u) : "f"(f));
    return u;
}

__device__ __forceinline__ void mma_tf32_16n8k8(
    float d[4], const uint32_t a[4], const uint32_t b[2])
{
    asm volatile(
        "mma.sync.aligned.m16n8k8.row.col.f32.tf32.tf32.f32 "
        "{%0,%1,%2,%3}, {%4,%5,%6,%7}, {%8,%9}, {%0,%1,%2,%3};"
        : "+f"(d[0]), "+f"(d[1]), "+f"(d[2]), "+f"(d[3])
        : "r"(a[0]), "r"(a[1]), "r"(a[2]), "r"(a[3]),
          "r"(b[0]), "r"(b[1]));
}

// ===================== Kernel A: QKV via tf32 mma.sync =====================
// 512 CTAs x 256 threads (8 warps: 2 M-groups x 4 N-groups).
// CTA tile: 128 rows x 192 cols (Q|K|V). Warp tile: 64 x 48.
// K loop: 32 chunks of 32, double-buffered SMEM.
// A smem stride 36 floats -> frag bank (4r+k)%32 conflict-free.
// B smem stride 200 floats -> frag bank (8k+n)%32 conflict-free.

#define SA_STRIDE 36
#define SB_STRIDE 200
#define SA_FLOATS (128*SA_STRIDE)                 // 4608
#define SB_FLOATS (32*SB_STRIDE)                  // 6400
#define BUF_FLOATS (SA_FLOATS + SB_FLOATS)        // 11008
#define QKV_SMEM (2*BUF_FLOATS*4)                 // 88064 bytes

__global__ __launch_bounds__(256) void qkv_mma_kernel(
    const float* __restrict__ x,
    const float* __restrict__ Wq,
    const float* __restrict__ Wk,
    const float* __restrict__ Wv)
{
    extern __shared__ uint32_t sm_u[];
    const int tid    = threadIdx.x;
    const int wid    = tid >> 5;
    const int lane   = tid & 31;
    const int warp_m = wid >> 2;       // 0..1
    const int warp_n = wid & 3;        // 0..3
    const int row0   = blockIdx.x * 128;

    const int lr = lane >> 2;          // 0..7
    const int lc = lane & 3;           // 0..3

    float acc[4][6][4];
    #pragma unroll
    for (int mt = 0; mt < 4; mt++)
        #pragma unroll
        for (int nt = 0; nt < 6; nt++)
            #pragma unroll
            for (int i = 0; i < 4; i++) acc[mt][nt][i] = 0.f;

    // staging helpers ------------------------------------------------------
    // A: 1024 float4 / 256 thr = 4 each. idx -> r = idx>>3, k4 = (idx&7)*4
    // B: 1536 float4 / 256 thr = 6 each. idx -> k = idx/48, nq = idx%48
    float4 ra[4], rb[6];

    auto ldg_chunk = [&](int kc) {
        #pragma unroll
        for (int l = 0; l < 4; l++) {
            int idx = tid + l * 256;
            int r   = idx >> 3;
            int k4  = (idx & 7) * 4;
            ra[l] = *(const float4*)&x[(size_t)(row0 + r) * CC + kc + k4];
        }
        #pragma unroll
        for (int l = 0; l < 6; l++) {
            int idx = tid + l * 256;
            int k   = idx / 48;
            int nq  = idx % 48;
            int m   = nq >> 4;                     // 0..2 (16 float4 per matrix)
            int col = (nq & 15) * 4;
            const float* W = (m == 0) ? Wq : (m == 1) ? Wk : Wv;
            rb[l] = *(const float4*)&W[(size_t)(kc + k) * DD + col];
        }
    };

    auto sts_chunk = [&](uint32_t* sA, uint32_t* sB) {
        #pragma unroll
        for (int l = 0; l < 4; l++) {
            int idx = tid + l * 256;
            int r   = idx >> 3;
            int k4  = (idx & 7) * 4;
            uint4 u = make_uint4(f32_to_tf32(ra[l].x), f32_to_tf32(ra[l].y),
                                 f32_to_tf32(ra[l].z), f32_to_tf32(ra[l].w));
            *(uint4*)(sA + r * SA_STRIDE + k4) = u;
        }
        #pragma unroll
        for (int l = 0; l < 6; l++) {
            int idx = tid + l * 256;
            int k   = idx / 48;
            int nq  = idx % 48;
            uint4 u = make_uint4(f32_to_tf32(rb[l].x), f32_to_tf32(rb[l].y),
                                 f32_to_tf32(rb[l].z), f32_to_tf32(rb[l].w));
            *(uint4*)(sB + k * SB_STRIDE + nq * 4) = u;
        }
    };

    // prologue: chunk 0 into buffer 0
    ldg_chunk(0);
    sts_chunk(sm_u, sm_u + SA_FLOATS);
    __syncthreads();

    for (int c = 0; c < 32; c++) {
        const int cur = c & 1;
        uint32_t* sAc = sm_u + cur * BUF_FLOATS;
        uint32_t* sBc = sAc + SA_FLOATS;

        // prefetch next chunk from global (hidden under mma)
        if (c + 1 < 32) ldg_chunk((c + 1) * 32);

        // compute this chunk: 4 k-steps of k=8
        #pragma unroll
        for (int ks = 0; ks < 4; ks++) {
            uint32_t af[4][4];
            #pragma unroll
            for (int mt = 0; mt < 4; mt++) {
                int r = warp_m * 64 + mt * 16 + lr;
                int k = ks * 8 + lc;
                const uint32_t* p = sAc + r * SA_STRIDE + k;
                af[mt][0] = p[0];
                af[mt][1] = p[8 * SA_STRIDE];
                af[mt][2] = p[4];
                af[mt][3] = p[8 * SA_STRIDE + 4];
            }
            uint32_t bf[6][2];
            #pragma unroll
            for (int nt = 0; nt < 6; nt++) {
                int n = warp_n * 48 + nt * 8 + lr;
                int k = ks * 8 + lc;
                const uint32_t* p = sBc + k * SB_STRIDE + n;
                bf[nt][0] = p[0];
                bf[nt][1] = p[4 * SB_STRIDE];
            }
            #pragma unroll
            for (int mt = 0; mt < 4; mt++)
                #pragma unroll
                for (int nt = 0; nt < 6; nt++)
                    mma_tf32_16n8k8(acc[mt][nt], af[mt], bf[nt]);
        }

        if (c + 1 < 32) {
            const int nxt = cur ^ 1;
            uint32_t* sAn = sm_u + nxt * BUF_FLOATS;
            sts_chunk(sAn, sAn + SA_FLOATS);
        }
        __syncthreads();
    }

    // epilogue: scatter accumulators to g_q / g_k / g_v
    #pragma unroll
    for (int mt = 0; mt < 4; mt++) {
        int rg = row0 + warp_m * 64 + mt * 16 + lr;
        #pragma unroll
        for (int nt = 0; nt < 6; nt++) {
            int ng = warp_n * 48 + nt * 8 + lc * 2;
            int m  = ng >> 6;
            int d  = ng & 63;
            float* base = (m == 0) ? g_q : (m == 1) ? g_k : g_v;
            *(float2*)&base[(size_t)rg * DD + d] =
                make_float2(acc[mt][nt][0], acc[mt][nt][1]);
            *(float2*)&base[(size_t)(rg + 8) * DD + d] =
                make_float2(acc[mt][nt][2], acc[mt][nt][3]);
        }
    }
}

// ---------------------------------------------------------------------------
// Kernel B: causal attention (unchanged from R1), one block per (batch, 64-q tile).
// ---------------------------------------------------------------------------
#define SQT_STRIDE 65
#define SP_STRIDE  257
#define SMEM_FLOATS (64*SQT_STRIDE + 256*64 + 256*64 + 64*SP_STRIDE)
#define SMEM_BYTES  (SMEM_FLOATS * 4)

__global__ __launch_bounds__(256) void attn_kernel(float* __restrict__ out)
{
    extern __shared__ float sm[];
    float* sQt = sm;                        // [d][r], stride 65
    float* sK  = sQt + 64 * SQT_STRIDE;     // [s][d]
    float* sV  = sK  + 256 * 64;            // [s][d]
    float* sP  = sV  + 256 * 64;            // [r][s], stride 257

    const int tid = threadIdx.x;
    const int bb  = blockIdx.y;
    const int q0  = blockIdx.x * 64;

    const float* kbase = g_k + (size_t)bb * TT * DD;
    const float* vbase = g_v + (size_t)bb * TT * DD;
    #pragma unroll
    for (int l = 0; l < 16; l++) {
        int idx = tid + l * 256;
        int s   = idx >> 4;
        int d4  = idx & 15;
        *(float4*)&sK[s*64 + d4*4] = *(const float4*)&kbase[s*DD + d4*4];
        *(float4*)&sV[s*64 + d4*4] = *(const float4*)&vbase[s*DD + d4*4];
    }
    const float* qbase = g_q + (size_t)(bb * TT + q0) * DD;
    #pragma unroll
    for (int l = 0; l < 4; l++) {
        int idx = tid + l * 256;
        int r   = idx >> 4;
        int d4  = idx & 15;
        float4 qv = *(const float4*)&qbase[r*DD + d4*4];
        sQt[(d4*4+0)*SQT_STRIDE + r] = qv.x;
        sQt[(d4*4+1)*SQT_STRIDE + r] = qv.y;
        sQt[(d4*4+2)*SQT_STRIDE + r] = qv.z;
        sQt[(d4*4+3)*SQT_STRIDE + r] = qv.w;
    }
    __syncthreads();

    const int tx = tid & 15;
    const int ty = tid >> 4;
    {
        float acc[4][16];
        #pragma unroll
        for (int i = 0; i < 4; i++)
            #pragma unroll
            for (int j = 0; j < 16; j++) acc[i][j] = 0.f;

        #pragma unroll 4
        for (int d = 0; d < 64; d++) {
            float a[4];
            #pragma unroll
            for (int i = 0; i < 4; i++) a[i] = sQt[d*SQT_STRIDE + tx + 16*i];
            float b[16];
            #pragma unroll
            for (int j = 0; j < 16; j++) b[j] = sK[(ty*16 + j)*64 + d];
            #pragma unroll
            for (int i = 0; i < 4; i++)
                #pragma unroll
                for (int j = 0; j < 16; j++)
                    acc[i][j] = fmaf(a[i], b[j], acc[i][j]);
        }

        const float scale = 0.03125f;
        #pragma unroll
        for (int i = 0; i < 4; i++) {
            int r = tx + 16*i;
            #pragma unroll
            for (int j = 0; j < 16; j++) {
                int s = ty*16 + j;
                float sc = acc[i][j] * scale;
                if (s > q0 + r) sc = -INFINITY;
                sP[r*SP_STRIDE + s] = sc;
            }
        }
    }
    __syncthreads();

    if (tid < 64) {
        float m = -INFINITY;
        for (int s = 0; s < 256; s++) m = fmaxf(m, sP[tid*SP_STRIDE + s]);
        float sum = 0.f;
        for (int s = 0; s < 256; s++) {
            float e = expf(sP[tid*SP_STRIDE + s] - m);
            sP[tid*SP_STRIDE + s] = e;
            sum += e;
        }
        float inv = 1.f / sum;
        for (int s = 0; s < 256; s++) sP[tid*SP_STRIDE + s] *= inv;
    }
    __syncthreads();

    {
        float oacc[4][4];
        #pragma unroll
        for (int i = 0; i < 4; i++)
            #pragma unroll
            for (int j = 0; j < 4; j++) oacc[i][j] = 0.f;

        #pragma unroll 4
        for (int s = 0; s < 256; s++) {
            float4 bv = *(const float4*)&sV[s*64 + tx*4];
            float a[4];
            #pragma unroll
            for (int i = 0; i < 4; i++) a[i] = sP[(ty*4 + i)*SP_STRIDE + s];
            #pragma unroll
            for (int i = 0; i < 4; i++) {
                oacc[i][0] = fmaf(a[i], bv.x, oacc[i][0]);
                oacc[i][1] = fmaf(a[i], bv.y, oacc[i][1]);
                oacc[i][2] = fmaf(a[i], bv.z, oacc[i][2]);
                oacc[i][3] = fmaf(a[i], bv.w, oacc[i][3]);
            }
        }

        #pragma unroll
        for (int i = 0; i < 4; i++) {
            size_t o = (size_t)(bb * TT + q0 + ty*4 + i) * DD + tx*4;
            *(float4*)&out[o] = make_float4(oacc[i][0], oacc[i][1],
                                            oacc[i][2], oacc[i][3]);
        }
    }
}

// ---------------------------------------------------------------------------
extern "C" void kernel_launch(void* const* d_in, const int* in_sizes, int n_in,
                              void* d_out, int out_size)
{
    (void)in_sizes; (void)n_in; (void)out_size;
    const float* x  = (const float*)d_in[0];
    const float* Wq = (const float*)d_in[1];
    const float* Wk = (const float*)d_in[2];
    const float* Wv = (const float*)d_in[3];
    float* out = (float*)d_out;

    cudaFuncSetAttribute(qkv_mma_kernel,
                         cudaFuncAttributeMaxDynamicSharedMemorySize, QKV_SMEM);
    cudaFuncSetAttribute(attn_kernel,
                         cudaFuncAttributeMaxDynamicSharedMemorySize, SMEM_BYTES);

    qkv_mma_kernel<<<BT / 128, 256, QKV_SMEM>>>(x, Wq, Wk, Wv);
    attn_kernel<<<dim3(4, BB), 256, SMEM_BYTES>>>(out);
}

// round 4
// speedup vs baseline: 3.1740x; 1.3504x over previous
#include <cuda_runtime.h>
#include <math.h>
#include <cstdint>

#define BB 256
#define TT 256
#define CC 1024
#define DD 64
#define BT (BB*TT)

// Scratch for Q, K, V (16 MB each)
__device__ float g_q[BT*DD];
__device__ float g_k[BT*DD];
__device__ float g_v[BT*DD];

// ===================== mma.sync helpers (sm_80+ PTX) =======================
__device__ __forceinline__ uint32_t f32_to_tf32(float f) {
    uint32_t u;
    asm("cvt.rna.tf32.f32 %0, %1;" : "=r"(u) : "f"(f));
    return u;
}

__device__ __forceinline__ void mma_tf32_16n8k8(
    float d[4], const uint32_t a[4], const uint32_t b[2])
{
    asm volatile(
        "mma.sync.aligned.m16n8k8.row.col.f32.tf32.tf32.f32 "
        "{%0,%1,%2,%3}, {%4,%5,%6,%7}, {%8,%9}, {%0,%1,%2,%3};"
        : "+f"(d[0]), "+f"(d[1]), "+f"(d[2]), "+f"(d[3])
        : "r"(a[0]), "r"(a[1]), "r"(a[2]), "r"(a[3]),
          "r"(b[0]), "r"(b[1]));
}

// ===================== Kernel A: QKV via tf32 mma.sync (unchanged) =========
#define SA_STRIDE 36
#define SB_STRIDE 200
#define SA_FLOATS (128*SA_STRIDE)
#define SB_FLOATS (32*SB_STRIDE)
#define BUF_FLOATS (SA_FLOATS + SB_FLOATS)
#define QKV_SMEM (2*BUF_FLOATS*4)

__global__ __launch_bounds__(256) void qkv_mma_kernel(
    const float* __restrict__ x,
    const float* __restrict__ Wq,
    const float* __restrict__ Wk,
    const float* __restrict__ Wv)
{
    extern __shared__ uint32_t sm_u[];
    const int tid    = threadIdx.x;
    const int wid    = tid >> 5;
    const int lane   = tid & 31;
    const int warp_m = wid >> 2;
    const int warp_n = wid & 3;
    const int row0   = blockIdx.x * 128;

    const int lr = lane >> 2;
    const int lc = lane & 3;

    float acc[4][6][4];
    #pragma unroll
    for (int mt = 0; mt < 4; mt++)
        #pragma unroll
        for (int nt = 0; nt < 6; nt++)
            #pragma unroll
            for (int i = 0; i < 4; i++) acc[mt][nt][i] = 0.f;

    float4 ra[4], rb[6];

    auto ldg_chunk = [&](int kc) {
        #pragma unroll
        for (int l = 0; l < 4; l++) {
            int idx = tid + l * 256;
            int r   = idx >> 3;
            int k4  = (idx & 7) * 4;
            ra[l] = *(const float4*)&x[(size_t)(row0 + r) * CC + kc + k4];
        }
        #pragma unroll
        for (int l = 0; l < 6; l++) {
            int idx = tid + l * 256;
            int k   = idx / 48;
            int nq  = idx % 48;
            int m   = nq >> 4;
            int col = (nq & 15) * 4;
            const float* W = (m == 0) ? Wq : (m == 1) ? Wk : Wv;
            rb[l] = *(const float4*)&W[(size_t)(kc + k) * DD + col];
        }
    };

    auto sts_chunk = [&](uint32_t* sA, uint32_t* sB) {
        #pragma unroll
        for (int l = 0; l < 4; l++) {
            int idx = tid + l * 256;
            int r   = idx >> 3;
            int k4  = (idx & 7) * 4;
            uint4 u = make_uint4(f32_to_tf32(ra[l].x), f32_to_tf32(ra[l].y),
                                 f32_to_tf32(ra[l].z), f32_to_tf32(ra[l].w));
            *(uint4*)(sA + r * SA_STRIDE + k4) = u;
        }
        #pragma unroll
        for (int l = 0; l < 6; l++) {
            int idx = tid + l * 256;
            int k   = idx / 48;
            int nq  = idx % 48;
            uint4 u = make_uint4(f32_to_tf32(rb[l].x), f32_to_tf32(rb[l].y),
                                 f32_to_tf32(rb[l].z), f32_to_tf32(rb[l].w));
            *(uint4*)(sB + k * SB_STRIDE + nq * 4) = u;
        }
    };

    ldg_chunk(0);
    sts_chunk(sm_u, sm_u + SA_FLOATS);
    __syncthreads();

    for (int c = 0; c < 32; c++) {
        const int cur = c & 1;
        uint32_t* sAc = sm_u + cur * BUF_FLOATS;
        uint32_t* sBc = sAc + SA_FLOATS;

        if (c + 1 < 32) ldg_chunk((c + 1) * 32);

        #pragma unroll
        for (int ks = 0; ks < 4; ks++) {
            uint32_t af[4][4];
            #pragma unroll
            for (int mt = 0; mt < 4; mt++) {
                int r = warp_m * 64 + mt * 16 + lr;
                int k = ks * 8 + lc;
                const uint32_t* p = sAc + r * SA_STRIDE + k;
                af[mt][0] = p[0];
                af[mt][1] = p[8 * SA_STRIDE];
                af[mt][2] = p[4];
                af[mt][3] = p[8 * SA_STRIDE + 4];
            }
            uint32_t bf[6][2];
            #pragma unroll
            for (int nt = 0; nt < 6; nt++) {
                int n = warp_n * 48 + nt * 8 + lr;
                int k = ks * 8 + lc;
                const uint32_t* p = sBc + k * SB_STRIDE + n;
                bf[nt][0] = p[0];
                bf[nt][1] = p[4 * SB_STRIDE];
            }
            #pragma unroll
            for (int mt = 0; mt < 4; mt++)
                #pragma unroll
                for (int nt = 0; nt < 6; nt++)
                    mma_tf32_16n8k8(acc[mt][nt], af[mt], bf[nt]);
        }

        if (c + 1 < 32) {
            const int nxt = cur ^ 1;
            uint32_t* sAn = sm_u + nxt * BUF_FLOATS;
            sts_chunk(sAn, sAn + SA_FLOATS);
        }
        __syncthreads();
    }

    #pragma unroll
    for (int mt = 0; mt < 4; mt++) {
        int rg = row0 + warp_m * 64 + mt * 16 + lr;
        #pragma unroll
        for (int nt = 0; nt < 6; nt++) {
            int ng = warp_n * 48 + nt * 8 + lc * 2;
            int m  = ng >> 6;
            int d  = ng & 63;
            float* base = (m == 0) ? g_q : (m == 1) ? g_k : g_v;
            *(float2*)&base[(size_t)rg * DD + d] =
                make_float2(acc[mt][nt][0], acc[mt][nt][1]);
            *(float2*)&base[(size_t)(rg + 8) * DD + d] =
                make_float2(acc[mt][nt][2], acc[mt][nt][3]);
        }
    }
}

// ===================== Kernel B: attention via tf32 mma.sync ===============
// Grid (4, 256): q-tile x batch. 256 threads = 8 warps:
// warp_m = wid>>1 (16 rows each), warp_n = wid&1 (128 keys each).
// K smem [s][d] stride 68 (banks 4lr+lc for B-frags of QK^T).
// V smem [s][d] stride 72 (banks 8lc+lr for B-frags of PV).
// P reuses K region, stride 260 (banks 4lr+lc for A-frags).
// O cross-warp_n reduction reuses the same region, stride 66.

#define SK_STRIDE 68
#define SV_STRIDE 72
#define SP_STRIDE2 260
#define SO_STRIDE 66
#define SK_OFF 0
#define SK_SIZE (256*SK_STRIDE)            // 17408 u32
#define SV_OFF SK_SIZE
#define SV_SIZE (256*SV_STRIDE)            // 18432 u32
#define RED_OFF (SV_OFF + SV_SIZE)         // 35840
#define ATT_SMEM ((RED_OFF + 256) * 4)     // 144384 bytes

__global__ __launch_bounds__(256) void attn_kernel(float* __restrict__ out)
{
    extern __shared__ uint32_t smu[];
    uint32_t* sK   = smu + SK_OFF;
    uint32_t* sV   = smu + SV_OFF;
    float*    sRed = (float*)(smu + RED_OFF);    // [0:128) max, [128:256) sum
    uint32_t* sP   = smu + SK_OFF;               // reuse
    float*    sO   = (float*)(smu + SK_OFF);     // reuse (after P dead)

    const int tid  = threadIdx.x;
    const int wid  = tid >> 5;
    const int lane = tid & 31;
    const int wm   = wid >> 1;          // 0..3
    const int wn   = wid & 1;           // 0..1
    const int lr   = lane >> 2;         // 0..7
    const int lc   = lane & 3;          // 0..3

    const int qt = blockIdx.x;          // 0..3
    const int bb = blockIdx.y;          // batch
    const int q0 = qt * 64;

    // ---- stage K, V into smem (tf32) ----
    const float* kb = g_k + (size_t)bb * TT * DD;
    const float* vb = g_v + (size_t)bb * TT * DD;
    #pragma unroll
    for (int l = 0; l < 16; l++) {
        int idx = tid + l * 256;
        int s   = idx >> 4;
        int d4  = idx & 15;
        float4 kv = *(const float4*)&kb[s * DD + d4 * 4];
        float4 vv = *(const float4*)&vb[s * DD + d4 * 4];
        *(uint4*)(sK + s * SK_STRIDE + d4 * 4) =
            make_uint4(f32_to_tf32(kv.x), f32_to_tf32(kv.y),
                       f32_to_tf32(kv.z), f32_to_tf32(kv.w));
        *(uint4*)(sV + s * SV_STRIDE + d4 * 4) =
            make_uint4(f32_to_tf32(vv.x), f32_to_tf32(vv.y),
                       f32_to_tf32(vv.z), f32_to_tf32(vv.w));
    }

    // ---- Q fragments from gmem (tf32) ----
    uint32_t qf[8][4];
    {
        const size_t gr = (size_t)(bb * TT + q0 + wm * 16 + lr) * DD;
        #pragma unroll
        for (int ks = 0; ks < 8; ks++) {
            int k = ks * 8 + lc;
            qf[ks][0] = f32_to_tf32(g_q[gr + k]);
            qf[ks][1] = f32_to_tf32(g_q[gr + 8 * DD + k]);
            qf[ks][2] = f32_to_tf32(g_q[gr + k + 4]);
            qf[ks][3] = f32_to_tf32(g_q[gr + 8 * DD + k + 4]);
        }
    }
    __syncthreads();

    // valid n-tiles for this warp (causal): s-tile base <= q0+63
    const int ntv = min(16, max(0, (q0 + 64 - wn * 128) / 8));

    // ---- QK^T: scores in fragments ----
    float sacc[16][4];
    #pragma unroll
    for (int nt = 0; nt < 16; nt++)
        #pragma unroll
        for (int i = 0; i < 4; i++) sacc[nt][i] = 0.f;

    #pragma unroll
    for (int nt = 0; nt < 16; nt++) {
        if (nt >= ntv) break;
        const uint32_t* kp = sK + (wn * 128 + nt * 8 + lr) * SK_STRIDE;
        #pragma unroll
        for (int ks = 0; ks < 8; ks++) {
            uint32_t bfr[2];
            bfr[0] = kp[ks * 8 + lc];
            bfr[1] = kp[ks * 8 + lc + 4];
            mma_tf32_16n8k8(sacc[nt], qf[ks], bfr);
        }
    }

    // ---- scale + causal mask + row max ----
    const int row_g0 = q0 + wm * 16 + lr;      // global query row (low)
    float mrow[2] = {-INFINITY, -INFINITY};
    #pragma unroll
    for (int nt = 0; nt < 16; nt++) {
        if (nt >= ntv) break;
        #pragma unroll
        for (int i = 0; i < 4; i++) {
            int col = wn * 128 + nt * 8 + 2 * lc + (i & 1);
            int row = row_g0 + ((i >> 1) << 3);
            float v = sacc[nt][i] * 0.03125f;
            v = (col <= row) ? v : -INFINITY;
            sacc[nt][i] = v;
            if (i < 2) mrow[0] = fmaxf(mrow[0], v);
            else       mrow[1] = fmaxf(mrow[1], v);
        }
    }
    #pragma unroll
    for (int off = 1; off <= 2; off <<= 1) {
        mrow[0] = fmaxf(mrow[0], __shfl_xor_sync(0xFFFFFFFF, mrow[0], off));
        mrow[1] = fmaxf(mrow[1], __shfl_xor_sync(0xFFFFFFFF, mrow[1], off));
    }
    if (lc == 0) {
        sRed[wn * 64 + wm * 16 + lr]     = mrow[0];
        sRed[wn * 64 + wm * 16 + lr + 8] = mrow[1];
    }
    __syncthreads();

    float gm0 = fmaxf(sRed[wm * 16 + lr],     sRed[64 + wm * 16 + lr]);
    float gm1 = fmaxf(sRed[wm * 16 + lr + 8], sRed[64 + wm * 16 + lr + 8]);

    // ---- exp, store P (tf32, reusing K region), partial row sums ----
    float srow[2] = {0.f, 0.f};
    #pragma unroll
    for (int nt = 0; nt < 16; nt++) {
        if (nt >= ntv) break;
        float e0 = __expf(sacc[nt][0] - gm0);
        float e1 = __expf(sacc[nt][1] - gm0);
        float e2 = __expf(sacc[nt][2] - gm1);
        float e3 = __expf(sacc[nt][3] - gm1);
        srow[0] += e0 + e1;
        srow[1] += e2 + e3;
        uint32_t* p0 = sP + (wm * 16 + lr) * SP_STRIDE2 + wn * 128 + nt * 8 + 2 * lc;
        *(uint2*)p0 = make_uint2(f32_to_tf32(e0), f32_to_tf32(e1));
        uint32_t* p1 = p0 + 8 * SP_STRIDE2;
        *(uint2*)p1 = make_uint2(f32_to_tf32(e2), f32_to_tf32(e3));
    }
    #pragma unroll
    for (int off = 1; off <= 2; off <<= 1) {
        srow[0] += __shfl_xor_sync(0xFFFFFFFF, srow[0], off);
        srow[1] += __shfl_xor_sync(0xFFFFFFFF, srow[1], off);
    }
    if (lc == 0) {
        sRed[128 + wn * 64 + wm * 16 + lr]     = srow[0];
        sRed[128 + wn * 64 + wm * 16 + lr + 8] = srow[1];
    }
    __syncthreads();

    const float inv0 = 1.f / (sRed[128 + wm * 16 + lr] +
                              sRed[128 + 64 + wm * 16 + lr]);
    const float inv1 = 1.f / (sRed[128 + wm * 16 + lr + 8] +
                              sRed[128 + 64 + wm * 16 + lr + 8]);

    // ---- PV: O partial over this warp's 128-key half ----
    float oacc[8][4];
    #pragma unroll
    for (int nt = 0; nt < 8; nt++)
        #pragma unroll
        for (int i = 0; i < 4; i++) oacc[nt][i] = 0.f;

    for (int ks = 0; ks < ntv; ks++) {
        uint32_t af[4];
        const uint32_t* ap = sP + (wm * 16 + lr) * SP_STRIDE2 + wn * 128 + ks * 8;
        af[0] = ap[lc];
        af[1] = ap[8 * SP_STRIDE2 + lc];
        af[2] = ap[lc + 4];
        af[3] = ap[8 * SP_STRIDE2 + lc + 4];
        const uint32_t* vp = sV + (wn * 128 + ks * 8 + lc) * SV_STRIDE;
        #pragma unroll
        for (int nt = 0; nt < 8; nt++) {
            uint32_t bfr[2];
            bfr[0] = vp[nt * 8 + lr];
            bfr[1] = vp[4 * SV_STRIDE + nt * 8 + lr];
            mma_tf32_16n8k8(oacc[nt], af, bfr);
        }
    }
    __syncthreads();   // everyone done with P region

    // ---- cross-warp_n reduction + output ----
    if (wn == 0) {
        #pragma unroll
        for (int nt = 0; nt < 8; nt++) {
            float* o0 = sO + (wm * 16 + lr) * SO_STRIDE + nt * 8 + 2 * lc;
            *(float2*)o0 = make_float2(oacc[nt][0], oacc[nt][1]);
            float* o1 = o0 + 8 * SO_STRIDE;
            *(float2*)o1 = make_float2(oacc[nt][2], oacc[nt][3]);
        }
    }
    __syncthreads();
    if (wn == 1) {
        const size_t orow = (size_t)(bb * TT + q0 + wm * 16 + lr) * DD;
        #pragma unroll
        for (int nt = 0; nt < 8; nt++) {
            const float* o0 = sO + (wm * 16 + lr) * SO_STRIDE + nt * 8 + 2 * lc;
            const float* o1 = o0 + 8 * SO_STRIDE;
            float2 r0 = make_float2((oacc[nt][0] + o0[0]) * inv0,
                                    (oacc[nt][1] + o0[1]) * inv0);
            float2 r1 = make_float2((oacc[nt][2] + o1[0]) * inv1,
                                    (oacc[nt][3] + o1[1]) * inv1);
            *(float2*)&out[orow + nt * 8 + 2 * lc] = r0;
            *(float2*)&out[orow + 8 * DD + nt * 8 + 2 * lc] = r1;
        }
    }
}

// ---------------------------------------------------------------------------
extern "C" void kernel_launch(void* const* d_in, const int* in_sizes, int n_in,
                              void* d_out, int out_size)
{
    (void)in_sizes; (void)n_in; (void)out_size;
    const float* x  = (const float*)d_in[0];
    const float* Wq = (const float*)d_in[1];
    const float* Wk = (const float*)d_in[2];
    const float* Wv = (const float*)d_in[3];
    float* out = (float*)d_out;

    cudaFuncSetAttribute(qkv_mma_kernel,
                         cudaFuncAttributeMaxDynamicSharedMemorySize, QKV_SMEM);
    cudaFuncSetAttribute(attn_kernel,
                         cudaFuncAttributeMaxDynamicSharedMemorySize, ATT_SMEM);

    qkv_mma_kernel<<<BT / 128, 256, QKV_SMEM>>>(x, Wq, Wk, Wv);
    attn_kernel<<<dim3(4, BB), 256, ATT_SMEM>>>(out);
}

// round 5
// speedup vs baseline: 4.1260x; 1.2999x over previous
#include <cuda_runtime.h>
#include <math.h>
#include <cstdint>

#define BB 256
#define TT 256
#define CC 1024
#define DD 64
#define BT (BB*TT)

// Scratch: Q, K, V (16 MB each) + transposed weights (768 KB)
__device__ float g_q[BT*DD];
__device__ float g_k[BT*DD];
__device__ float g_v[BT*DD];
__device__ float g_wt[192*1024];   // rows 0-63: Wq^T, 64-127: Wk^T, 128-191: Wv^T

// ===================== PTX helpers (sm_80+ PTX, ok on compute_103) =========
__device__ __forceinline__ uint32_t f32_to_tf32(float f) {
    uint32_t u;
    asm("cvt.rna.tf32.f32 %0, %1;" : "=r"(u) : "f"(f));
    return u;
}

__device__ __forceinline__ void mma_tf32_16n8k8(
    float d[4], const uint32_t a[4], const uint32_t b[2])
{
    asm volatile(
        "mma.sync.aligned.m16n8k8.row.col.f32.tf32.tf32.f32 "
        "{%0,%1,%2,%3}, {%4,%5,%6,%7}, {%8,%9}, {%0,%1,%2,%3};"
        : "+f"(d[0]), "+f"(d[1]), "+f"(d[2]), "+f"(d[3])
        : "r"(a[0]), "r"(a[1]), "r"(a[2]), "r"(a[3]),
          "r"(b[0]), "r"(b[1]));
}

__device__ __forceinline__ void ldmatrix_x4(uint32_t r[4], uint32_t addr) {
    asm volatile("ldmatrix.sync.aligned.m8n8.x4.shared.b16 {%0,%1,%2,%3}, [%4];"
        : "=r"(r[0]), "=r"(r[1]), "=r"(r[2]), "=r"(r[3]) : "r"(addr));
}

__device__ __forceinline__ void cp_async16(uint32_t dst, const void* src) {
    asm volatile("cp.async.cg.shared.global [%0], [%1], 16;"
        :: "r"(dst), "l"(src) : "memory");
}
#define CP_COMMIT() asm volatile("cp.async.commit_group;" ::: "memory")
#define CP_WAIT1()  asm volatile("cp.async.wait_group 1;" ::: "memory")

__device__ __forceinline__ uint32_t smem_u32(const void* p) {
    uint32_t a;
    asm("{ .reg .u64 t; cvta.to.shared.u64 t, %1; cvt.u32.u64 %0, t; }"
        : "=r"(a) : "l"(p));
    return a;
}

// ===================== Kernel 0: transpose W into K-major ==================
__global__ __launch_bounds__(256) void transpose_w_kernel(
    const float* __restrict__ Wq, const float* __restrict__ Wk,
    const float* __restrict__ Wv)
{
    int n = blockIdx.x;                                 // 0..191
    const float* W = (n < 64) ? Wq : ((n < 128) ? Wk : Wv);
    int col = n & 63;
    for (int k = threadIdx.x; k < 1024; k += 256)
        g_wt[(size_t)n * 1024 + k] = W[(size_t)k * 64 + col];
}

// ===================== Kernel A: QKV via tf32 mma + cp.async + ldmatrix ====
// 512 CTAs x 256 thr (8 warps = 2 M x 4 N). CTA tile 128x192, warp 64x48.
// 32 K-chunks of 32, 2-stage cp.async pipeline. Both A (x) and B (Wt) staged
// as [row][k] fp32 at stride 36 floats (144B): ldmatrix conflict-free,
// cp.async 16B-aligned. tf32 truncation happens in HW.

#define STRW 36
#define A_ROWS 128
#define B_ROWS 192
#define CHUNK_BYTES ((A_ROWS + B_ROWS) * STRW * 4)   // 46080
#define B_OFF (A_ROWS * STRW * 4)                    // 18432
#define QKV_SMEM (2 * CHUNK_BYTES)                   // 92160

__global__ __launch_bounds__(256, 2) void qkv_mma_kernel(
    const float* __restrict__ x)
{
    extern __shared__ float smf[];
    const uint32_t sbase = smem_u32(smf);
    const int tid    = threadIdx.x;
    const int lane   = tid & 31;
    const int wid    = tid >> 5;
    const int warp_m = wid >> 2;       // 0..1
    const int warp_n = wid & 3;        // 0..3
    const int row0   = blockIdx.x * 128;

    const int lr = lane >> 2;
    const int lc = lane & 3;

    float acc[4][6][4];
    #pragma unroll
    for (int mt = 0; mt < 4; mt++)
        #pragma unroll
        for (int nt = 0; nt < 6; nt++)
            #pragma unroll
            for (int i = 0; i < 4; i++) acc[mt][nt][i] = 0.f;

    // cp.async issue: A 1024 segs (4/thr), B 1536 segs (6/thr)
    const int a_r   = tid >> 3;                  // base row, +32 per l (stride via l)
    const int a_seg = tid & 7;
    auto issue_chunk = [&](int c, uint32_t buf) {
        const int kc = c * 32;
        #pragma unroll
        for (int l = 0; l < 4; l++) {
            int r = a_r + l * 32;
            cp_async16(buf + (uint32_t)(r * STRW + a_seg * 4) * 4,
                       &x[(size_t)(row0 + r) * CC + kc + a_seg * 4]);
        }
        #pragma unroll
        for (int l = 0; l < 6; l++) {
            int n = a_r + l * 32;                // 0..191
            cp_async16(buf + B_OFF + (uint32_t)(n * STRW + a_seg * 4) * 4,
                       &g_wt[(size_t)n * 1024 + kc + a_seg * 4]);
        }
    };

    // ldmatrix per-thread address offsets (bytes)
    const uint32_t aoff =
        ((uint32_t)(warp_m * 64 + (lane & 15)) * STRW + (lane >> 4) * 4) * 4;
    const uint32_t boff =
        ((uint32_t)(warp_n * 48 + (lane & 7) + (lane >> 4) * 8) * STRW
         + ((lane >> 3) & 1) * 4) * 4;

    issue_chunk(0, sbase);             CP_COMMIT();
    issue_chunk(1, sbase + CHUNK_BYTES); CP_COMMIT();

    for (int c = 0; c < 32; c++) {
        CP_WAIT1();
        __syncthreads();

        const uint32_t buf   = sbase + (uint32_t)(c & 1) * CHUNK_BYTES;
        const uint32_t abase = buf + aoff;
        const uint32_t bbase = buf + B_OFF + boff;

        #pragma unroll
        for (int ks = 0; ks < 4; ks++) {
            uint32_t af[4][4];
            #pragma unroll
            for (int mt = 0; mt < 4; mt++)
                ldmatrix_x4(af[mt], abase + mt * (16 * STRW * 4) + ks * 32);
            uint32_t bf[12];
            #pragma unroll
            for (int j = 0; j < 3; j++)
                ldmatrix_x4(&bf[j * 4], bbase + j * (16 * STRW * 4) + ks * 32);
            #pragma unroll
            for (int mt = 0; mt < 4; mt++)
                #pragma unroll
                for (int nt = 0; nt < 6; nt++)
                    mma_tf32_16n8k8(acc[mt][nt], af[mt],
                                    &bf[(nt >> 1) * 4 + (nt & 1) * 2]);
        }
        __syncthreads();

        if (c + 2 < 32) issue_chunk(c + 2, buf);
        CP_COMMIT();
    }

    // epilogue: scatter accumulators to g_q / g_k / g_v
    #pragma unroll
    for (int mt = 0; mt < 4; mt++) {
        int rg = row0 + warp_m * 64 + mt * 16 + lr;
        #pragma unroll
        for (int nt = 0; nt < 6; nt++) {
            int ng = warp_n * 48 + nt * 8 + lc * 2;
            int m  = ng >> 6;
            int d  = ng & 63;
            float* base = (m == 0) ? g_q : (m == 1) ? g_k : g_v;
            *(float2*)&base[(size_t)rg * DD + d] =
                make_float2(acc[mt][nt][0], acc[mt][nt][1]);
            *(float2*)&base[(size_t)(rg + 8) * DD + d] =
                make_float2(acc[mt][nt][2], acc[mt][nt][3]);
        }
    }
}

// ===================== Kernel B: attention via tf32 mma.sync (unchanged) ===
#define SK_STRIDE 68
#define SV_STRIDE 72
#define SP_STRIDE2 260
#define SO_STRIDE 66
#define SK_OFF 0
#define SK_SIZE (256*SK_STRIDE)
#define SV_OFF SK_SIZE
#define SV_SIZE (256*SV_STRIDE)
#define RED_OFF (SV_OFF + SV_SIZE)
#define ATT_SMEM ((RED_OFF + 256) * 4)

__global__ __launch_bounds__(256) void attn_kernel(float* __restrict__ out)
{
    extern __shared__ uint32_t smu[];
    uint32_t* sK   = smu + SK_OFF;
    uint32_t* sV   = smu + SV_OFF;
    float*    sRed = (float*)(smu + RED_OFF);
    uint32_t* sP   = smu + SK_OFF;
    float*    sO   = (float*)(smu + SK_OFF);

    const int tid  = threadIdx.x;
    const int wid  = tid >> 5;
    const int lane = tid & 31;
    const int wm   = wid >> 1;
    const int wn   = wid & 1;
    const int lr   = lane >> 2;
    const int lc   = lane & 3;

    const int qt = blockIdx.x;
    const int bb = blockIdx.y;
    const int q0 = qt * 64;

    const float* kb = g_k + (size_t)bb * TT * DD;
    const float* vb = g_v + (size_t)bb * TT * DD;
    #pragma unroll
    for (int l = 0; l < 16; l++) {
        int idx = tid + l * 256;
        int s   = idx >> 4;
        int d4  = idx & 15;
        float4 kv = *(const float4*)&kb[s * DD + d4 * 4];
        float4 vv = *(const float4*)&vb[s * DD + d4 * 4];
        *(uint4*)(sK + s * SK_STRIDE + d4 * 4) =
            make_uint4(f32_to_tf32(kv.x), f32_to_tf32(kv.y),
                       f32_to_tf32(kv.z), f32_to_tf32(kv.w));
        *(uint4*)(sV + s * SV_STRIDE + d4 * 4) =
            make_uint4(f32_to_tf32(vv.x), f32_to_tf32(vv.y),
                       f32_to_tf32(vv.z), f32_to_tf32(vv.w));
    }

    uint32_t qf[8][4];
    {
        const size_t gr = (size_t)(bb * TT + q0 + wm * 16 + lr) * DD;
        #pragma unroll
        for (int ks = 0; ks < 8; ks++) {
            int k = ks * 8 + lc;
            qf[ks][0] = f32_to_tf32(g_q[gr + k]);
            qf[ks][1] = f32_to_tf32(g_q[gr + 8 * DD + k]);
            qf[ks][2] = f32_to_tf32(g_q[gr + k + 4]);
            qf[ks][3] = f32_to_tf32(g_q[gr + 8 * DD + k + 4]);
        }
    }
    __syncthreads();

    const int ntv = min(16, max(0, (q0 + 64 - wn * 128) / 8));

    float sacc[16][4];
    #pragma unroll
    for (int nt = 0; nt < 16; nt++)
        #pragma unroll
        for (int i = 0; i < 4; i++) sacc[nt][i] = 0.f;

    #pragma unroll
    for (int nt = 0; nt < 16; nt++) {
        if (nt >= ntv) break;
        const uint32_t* kp = sK + (wn * 128 + nt * 8 + lr) * SK_STRIDE;
        #pragma unroll
        for (int ks = 0; ks < 8; ks++) {
            uint32_t bfr[2];
            bfr[0] = kp[ks * 8 + lc];
            bfr[1] = kp[ks * 8 + lc + 4];
            mma_tf32_16n8k8(sacc[nt], qf[ks], bfr);
        }
    }

    const int row_g0 = q0 + wm * 16 + lr;
    float mrow[2] = {-INFINITY, -INFINITY};
    #pragma unroll
    for (int nt = 0; nt < 16; nt++) {
        if (nt >= ntv) break;
        #pragma unroll
        for (int i = 0; i < 4; i++) {
            int col = wn * 128 + nt * 8 + 2 * lc + (i & 1);
            int row = row_g0 + ((i >> 1) << 3);
            float v = sacc[nt][i] * 0.03125f;
            v = (col <= row) ? v : -INFINITY;
            sacc[nt][i] = v;
            if (i < 2) mrow[0] = fmaxf(mrow[0], v);
            else       mrow[1] = fmaxf(mrow[1], v);
        }
    }
    #pragma unroll
    for (int off = 1; off <= 2; off <<= 1) {
        mrow[0] = fmaxf(mrow[0], __shfl_xor_sync(0xFFFFFFFF, mrow[0], off));
        mrow[1] = fmaxf(mrow[1], __shfl_xor_sync(0xFFFFFFFF, mrow[1], off));
    }
    if (lc == 0) {
        sRed[wn * 64 + wm * 16 + lr]     = mrow[0];
        sRed[wn * 64 + wm * 16 + lr + 8] = mrow[1];
    }
    __syncthreads();

    float gm0 = fmaxf(sRed[wm * 16 + lr],     sRed[64 + wm * 16 + lr]);
    float gm1 = fmaxf(sRed[wm * 16 + lr + 8], sRed[64 + wm * 16 + lr + 8]);

    float srow[2] = {0.f, 0.f};
    #pragma unroll
    for (int nt = 0; nt < 16; nt++) {
        if (nt >= ntv) break;
        float e0 = __expf(sacc[nt][0] - gm0);
        float e1 = __expf(sacc[nt][1] - gm0);
        float e2 = __expf(sacc[nt][2] - gm1);
        float e3 = __expf(sacc[nt][3] - gm1);
        srow[0] += e0 + e1;
        srow[1] += e2 + e3;
        uint32_t* p0 = sP + (wm * 16 + lr) * SP_STRIDE2 + wn * 128 + nt * 8 + 2 * lc;
        *(uint2*)p0 = make_uint2(f32_to_tf32(e0), f32_to_tf32(e1));
        uint32_t* p1 = p0 + 8 * SP_STRIDE2;
        *(uint2*)p1 = make_uint2(f32_to_tf32(e2), f32_to_tf32(e3));
    }
    #pragma unroll
    for (int off = 1; off <= 2; off <<= 1) {
        srow[0] += __shfl_xor_sync(0xFFFFFFFF, srow[0], off);
        srow[1] += __shfl_xor_sync(0xFFFFFFFF, srow[1], off);
    }
    if (lc == 0) {
        sRed[128 + wn * 64 + wm * 16 + lr]     = srow[0];
        sRed[128 + wn * 64 + wm * 16 + lr + 8] = srow[1];
    }
    __syncthreads();

    const float inv0 = 1.f / (sRed[128 + wm * 16 + lr] +
                              sRed[128 + 64 + wm * 16 + lr]);
    const float inv1 = 1.f / (sRed[128 + wm * 16 + lr + 8] +
                              sRed[128 + 64 + wm * 16 + lr + 8]);

    float oacc[8][4];
    #pragma unroll
    for (int nt = 0; nt < 8; nt++)
        #pragma unroll
        for (int i = 0; i < 4; i++) oacc[nt][i] = 0.f;

    for (int ks = 0; ks < ntv; ks++) {
        uint32_t af[4];
        const uint32_t* ap = sP + (wm * 16 + lr) * SP_STRIDE2 + wn * 128 + ks * 8;
        af[0] = ap[lc];
        af[1] = ap[8 * SP_STRIDE2 + lc];
        af[2] = ap[lc + 4];
        af[3] = ap[8 * SP_STRIDE2 + lc + 4];
        const uint32_t* vp = sV + (wn * 128 + ks * 8 + lc) * SV_STRIDE;
        #pragma unroll
        for (int nt = 0; nt < 8; nt++) {
            uint32_t bfr[2];
            bfr[0] = vp[nt * 8 + lr];
            bfr[1] = vp[4 * SV_STRIDE + nt * 8 + lr];
            mma_tf32_16n8k8(oacc[nt], af, bfr);
        }
    }
    __syncthreads();

    if (wn == 0) {
        #pragma unroll
        for (int nt = 0; nt < 8; nt++) {
            float* o0 = sO + (wm * 16 + lr) * SO_STRIDE + nt * 8 + 2 * lc;
            *(float2*)o0 = make_float2(oacc[nt][0], oacc[nt][1]);
            float* o1 = o0 + 8 * SO_STRIDE;
            *(float2*)o1 = make_float2(oacc[nt][2], oacc[nt][3]);
        }
    }
    __syncthreads();
    if (wn == 1) {
        const size_t orow = (size_t)(bb * TT + q0 + wm * 16 + lr) * DD;
        #pragma unroll
        for (int nt = 0; nt < 8; nt++) {
            const float* o0 = sO + (wm * 16 + lr) * SO_STRIDE + nt * 8 + 2 * lc;
            const float* o1 = o0 + 8 * SO_STRIDE;
            float2 r0 = make_float2((oacc[nt][0] + o0[0]) * inv0,
                                    (oacc[nt][1] + o0[1]) * inv0);
            float2 r1 = make_float2((oacc[nt][2] + o1[0]) * inv1,
                                    (oacc[nt][3] + o1[1]) * inv1);
            *(float2*)&out[orow + nt * 8 + 2 * lc] = r0;
            *(float2*)&out[orow + 8 * DD + nt * 8 + 2 * lc] = r1;
        }
    }
}

// ---------------------------------------------------------------------------
extern "C" void kernel_launch(void* const* d_in, const int* in_sizes, int n_in,
                              void* d_out, int out_size)
{
    (void)in_sizes; (void)n_in; (void)out_size;
    const float* x  = (const float*)d_in[0];
    const float* Wq = (const float*)d_in[1];
    const float* Wk = (const float*)d_in[2];
    const float* Wv = (const float*)d_in[3];
    float* out = (float*)d_out;

    cudaFuncSetAttribute(qkv_mma_kernel,
                         cudaFuncAttributeMaxDynamicSharedMemorySize, QKV_SMEM);
    cudaFuncSetAttribute(attn_kernel,
                         cudaFuncAttributeMaxDynamicSharedMemorySize, ATT_SMEM);

    transpose_w_kernel<<<192, 256>>>(Wq, Wk, Wv);
    qkv_mma_kernel<<<BT / 128, 256, QKV_SMEM>>>(x);
    attn_kernel<<<dim3(4, BB), 256, ATT_SMEM>>>(out);
}